// round 7
// baseline (speedup 1.0000x reference)
#include <cuda_runtime.h>

// EMA scan h_t = a*x_t + (1-a)*h_{t-1}, T innermost. Warp-cooperative,
// coalesced, one warp per full row (single-wave grid = 1024 CTAs).
//
// R7: 6-stage per-warp cp.async ring in smem. Deep prefetch (3KB/warp in
// flight) without register pressure or front-batched-LDG spread. Each lane
// copies & consumes its own 16B -> no barriers needed. Truncated 3-step
// Kogge-Stone scan (dropped terms <= 0.6^32 ~ 8e-8).

#define A    0.4f
#define OMA  0.6f
#define OMA2 0.36f
#define OMA3 0.216f
#define OMA4 0.1296f
#define FULL   0xFFFFFFFFu
#define STAGES 6
#define WPB    8          // warps per block

__device__ __forceinline__ float tile_scan(float s3, int lane)
{
    float I = s3, u;
    u = __shfl_up_sync(FULL, I, 1);
    if (lane >= 1) I = fmaf(OMA4, u, I);            // 0.6^4
    u = __shfl_up_sync(FULL, I, 2);
    if (lane >= 2) I = fmaf(0.01679616f, u, I);     // 0.6^8
    u = __shfl_up_sync(FULL, I, 4);
    if (lane >= 4) I = fmaf(2.82110990e-4f, u, I);  // 0.6^16
    return I;
}

__global__ void __launch_bounds__(256, 7) ema_warp_kernel(
    const float* __restrict__ x,
    const float* __restrict__ h0,
    float* __restrict__ y,
    int T, int rows)
{
    __shared__ __align__(16) float4 ring[WPB][STAGES][32];

    int warp = threadIdx.x >> 5;
    int lane = threadIdx.x & 31;
    int row  = blockIdx.x * WPB + warp;
    if (row >= rows) return;

    const float4* xr = reinterpret_cast<const float4*>(x + (size_t)row * T);
    float4*       yr = reinterpret_cast<float4*>(y + (size_t)row * T);

    float h = h0[row];
    float d4L = __powf(OMA4, (float)lane);      // 0.6^(4*lane)
    const float d128 = 2.4633073e-29f;          // 0.6^128

    unsigned smem0 = (unsigned)__cvta_generic_to_shared(&ring[warp][0][lane]);

    int ntiles = T / 128;                       // 32

    // prologue: fill the ring
    #pragma unroll
    for (int s = 0; s < STAGES; s++) {
        unsigned dst = smem0 + s * 512u;
        const float4* src = xr + s * 32 + lane;
        asm volatile("cp.async.cg.shared.global [%0], [%1], 16;\n"
                     :: "r"(dst), "l"(src) : "memory");
        asm volatile("cp.async.commit_group;\n" ::: "memory");
    }

    int st = 0;
    #pragma unroll 1
    for (int t = 0; t < ntiles; t++) {
        // oldest group (tile t) complete -> its smem data is ready for this lane
        asm volatile("cp.async.wait_group %0;\n" :: "n"(STAGES - 1) : "memory");

        float4 v = ring[warp][st][lane];

        // lane-local weighted prefixes
        float s0 = A * v.x;
        float s1 = fmaf(A, v.y, OMA * s0);
        float s2 = fmaf(A, v.z, OMA * s1);
        float s3 = fmaf(A, v.w, OMA * s2);

        float I = tile_scan(s3, lane);
        float Bv = __shfl_up_sync(FULL, I, 1); if (lane == 0) Bv = 0.0f;
        float I31 = __shfl_sync(FULL, I, 31);

        float C = fmaf(d4L, h, Bv);
        float4 o;
        o.x = fmaf(OMA,  C, s0);
        o.y = fmaf(OMA2, C, s1);
        o.z = fmaf(OMA3, C, s2);
        o.w = fmaf(OMA4, C, s3);
        yr[t * 32 + lane] = o;

        h = fmaf(d128, h, I31);

        // refill this stage with tile t+STAGES (one group per iteration,
        // empty group when past the end keeps the pending count invariant)
        int pt = t + STAGES;
        if (pt < ntiles) {
            unsigned dst = smem0 + st * 512u;
            const float4* src = xr + pt * 32 + lane;
            asm volatile("cp.async.cg.shared.global [%0], [%1], 16;\n"
                         :: "r"(dst), "l"(src) : "memory");
        }
        asm volatile("cp.async.commit_group;\n" ::: "memory");

        st = (st == STAGES - 1) ? 0 : st + 1;
    }
}

extern "C" void kernel_launch(void* const* d_in, const int* in_sizes, int n_in,
                              void* d_out, int out_size)
{
    const float* x  = (const float*)d_in[0];   // inp    [B, D, T]
    const float* h0 = (const float*)d_in[1];   // hidden [B, D, 1]
    float* y = (float*)d_out;

    int rows = in_sizes[1];        // B*D = 8192
    int T = in_sizes[0] / rows;    // 4096

    int threads = WPB * 32;        // 256: 8 warps/block, 1 row/warp
    int blocks = (rows + WPB - 1) / WPB;   // 1024 -> single wave
    ema_warp_kernel<<<blocks, threads>>>(x, h0, y, T, rows);
}